// round 7
// baseline (speedup 1.0000x reference)
#include <cuda_runtime.h>
#include <cstdint>

#define QN 8192
#define SN 30
#define DN 512

constexpr int THREADS   = 896;             // 28 warps = 14 pairs
constexpr int GRID      = 148;
constexpr int ROWS      = 4;               // q rows per tile
constexpr int NTILE     = QN / ROWS;       // 2048
constexpr int DHALF     = 256;             // d per warp (pair splits d)
constexpr int QCHUNK    = 64;              // floats per row per staged chunk
constexpr int NCHUNK    = DHALF / QCHUNK;  // 4
constexpr int STRIDE    = 516;             // support smem stride: conflict-free
constexpr int PAIRS_BLK = 14;

typedef unsigned long long ull;

__device__ __forceinline__ ull psub(ull a, ull b) {
    ull r; asm("sub.rn.f32x2 %0, %1, %2;" : "=l"(r) : "l"(a), "l"(b)); return r;
}
__device__ __forceinline__ ull pfma(ull a, ull b, ull c) {
    ull r; asm("fma.rn.f32x2 %0, %1, %2, %3;" : "=l"(r) : "l"(a), "l"(b), "l"(c)); return r;
}
__device__ __forceinline__ float plo(ull a) { return __uint_as_float((unsigned)(a & 0xffffffffu)); }
__device__ __forceinline__ float phi(ull a) { return __uint_as_float((unsigned)(a >> 32)); }
__device__ __forceinline__ void cpasync16(uint32_t dst, const float* src) {
    asm volatile("cp.async.ca.shared.global [%0], [%1], 16;" :: "r"(dst), "l"(src));
}

#define ABS2 0x7fffffff7fffffffULL

__global__ __launch_bounds__(THREADS, 1)
void resus_kernel(const float* __restrict__ qenc,
                  const float* __restrict__ senc,
                  const float* __restrict__ sy,
                  const float* __restrict__ sp,
                  const float* __restrict__ qp,
                  const float* __restrict__ w,
                  const float* __restrict__ ascale,
                  const float* __restrict__ abias,
                  const int*   __restrict__ nsamp,
                  float* __restrict__ out)
{
    extern __shared__ float sh[];
    float* sT  = sh;                          // [32][STRIDE] supports (30 real + 2 zero)
    float* wSh = sT + 32 * STRIDE;            // [512]
    float* qB  = wSh + DN;                    // [28 warps][2 bufs][ROWS][QCHUNK]
    float* cmb = qB + 28 * 2 * ROWS * QCHUNK; // [14 pairs][2 halves][ROWS][32] float2

    const int tid  = threadIdx.x;
    const int lane = tid & 31;
    const int warp = tid >> 5;

    for (int idx = tid; idx < 32 * DN; idx += THREADS) {
        int s = idx >> 9, d = idx & (DN - 1);
        sT[s * STRIDE + d] = (s < SN) ? senc[idx] : 0.0f;
    }
    for (int d = tid; d < DN; d += THREADS) wSh[d] = w[d];

    float dyv = 0.0f;
    if (lane < SN) dyv = sy[lane] - 1.0f / (1.0f + __expf(-sp[lane]));
    const int ia = nsamp[0] - 1;
    const float scl = fabsf(ascale[ia]);
    const float bia = abias[ia];
    __syncthreads();

    const int pairIB = warp % 14;     // 0..13
    const int half   = warp / 14;     // 0 or 1
    const int tile   = blockIdx.x * PAIRS_BLK + pairIB;
    if (tile >= NTILE) return;

    const float* qbase = qenc + (size_t)tile * ROWS * DN + half * DHALF;
    float* qw = qB + warp * (2 * ROWS * QCHUNK);
    const uint32_t qwS = (uint32_t)__cvta_generic_to_shared(qw);
    const float* sRow = sT + lane * STRIDE + half * DHALF;
    const float* wRow = wSh + half * DHALF;

    ull aS[ROWS], aL[ROWS];
#pragma unroll
    for (int r = 0; r < ROWS; r++) { aS[r] = 0; aL[r] = 0; }

    // Stage one 4-row x 64-float chunk via cp.async (2 x 16B per lane).
    auto stageChunk = [&](int c, int b) {
#pragma unroll
        for (int i = 0; i < 2; i++) {
            int seg = lane + 32 * i;          // 0..63
            int r   = seg >> 4;               // 0..3
            int col = (seg & 15) * 4;         // 0..60
            const float* src = qbase + (size_t)r * DN + c * QCHUNK + col;
            uint32_t dst = qwS + (uint32_t)((b * ROWS * QCHUNK + r * QCHUNK + col) * 4);
            cpasync16(dst, src);
        }
        asm volatile("cp.async.commit_group;" ::: "memory");
    };

    auto computeChunk = [&](int c, int b) {
        const float* qbuf = qw + b * ROWS * QCHUNK;
        const float* sC   = sRow + c * QCHUNK;
        const float* wC   = wRow + c * QCHUNK;
#pragma unroll 8
        for (int t = 0; t < QCHUNK / 4; t++) {
            ulonglong2 sv = *reinterpret_cast<const ulonglong2*>(sC + t * 4);
            ulonglong2 wv = *reinterpret_cast<const ulonglong2*>(wC + t * 4);
#pragma unroll
            for (int r = 0; r < ROWS; r++) {
                ulonglong2 qv = *reinterpret_cast<const ulonglong2*>(qbuf + r * QCHUNK + t * 4);
                ull d0 = psub(qv.x, sv.x);
                ull d1 = psub(qv.y, sv.y);
                aL[r] = pfma(d0, d0, aL[r]);
                aL[r] = pfma(d1, d1, aL[r]);
                aS[r] = pfma(d0 & ABS2, wv.x, aS[r]);
                aS[r] = pfma(d1 & ABS2, wv.y, aS[r]);
            }
        }
    };

    // Per-warp rotated chunk order: decorrelates DRAM stage bursts and stall
    // windows across warps (accumulation order is commutative-safe here).
    const int rot = warp & (NCHUNK - 1);
    stageChunk(rot, 0);
#pragma unroll
    for (int k = 0; k < NCHUNK; k++) {
        if (k + 1 < NCHUNK) {
            stageChunk((k + 1 + rot) & (NCHUNK - 1), (k + 1) & 1);
            asm volatile("cp.async.wait_group 1;" ::: "memory");
        } else {
            asm volatile("cp.async.wait_group 0;" ::: "memory");
        }
        __syncwarp();
        computeChunk((k + rot) & (NCHUNK - 1), k & 1);
    }

    // ---- Pair combine: partials per (row, lane=support), sqrt AFTER combining ----
    float2* cp2 = reinterpret_cast<float2*>(cmb) + pairIB * (2 * ROWS * 32);
#pragma unroll
    for (int r = 0; r < ROWS; r++) {
        float scP  = plo(aS[r]) + phi(aS[r]);
        float ssqP = plo(aL[r]) + phi(aL[r]);
        cp2[(half * ROWS + r) * 32 + lane] = make_float2(scP, ssqP);
    }
    asm volatile("bar.sync %0, 64;" :: "r"(1 + pairIB) : "memory");

    // Each warp of the pair finishes 2 rows.
#pragma unroll
    for (int k = 0; k < 2; k++) {
        const int r = half * 2 + k;
        float2 pa = cp2[(0 * ROWS + r) * 32 + lane];
        float2 pb = cp2[(1 * ROWS + r) * 32 + lane];
        float sc  = pa.x + pb.x;
        float l2v = __fsqrt_rn(pa.y + pb.y);
        if (lane >= SN) { sc = -3.4e38f; l2v = 0.0f; }

        float m = sc;
#pragma unroll
        for (int d = 16; d; d >>= 1) m = fmaxf(m, __shfl_xor_sync(0xffffffffu, m, d));
        float e  = __expf(sc - m);
        float se = e, sd = e * dyv, sl = l2v;
#pragma unroll
        for (int d = 16; d; d >>= 1) {
            se += __shfl_xor_sync(0xffffffffu, se, d);
            sd += __shfl_xor_sync(0xffffffffu, sd, d);
            sl += __shfl_xor_sync(0xffffffffu, sl, d);
        }
        if (lane == 0) {
            const int row = tile * ROWS + r;
            out[row]      = (sd / se) * scl + bia + qp[row];
            out[QN + row] = sl * (1.0f / (float)SN);
        }
    }
}

extern "C" void kernel_launch(void* const* d_in, const int* in_sizes, int n_in,
                              void* d_out, int out_size) {
    const float* qenc   = (const float*)d_in[0];
    const float* senc   = (const float*)d_in[1];
    const float* sy     = (const float*)d_in[2];
    const float* sp     = (const float*)d_in[3];
    const float* qp     = (const float*)d_in[4];
    const float* w      = (const float*)d_in[5];
    // d_in[6] = fc1_b (softmax-invariant, unused)
    const float* ascale = (const float*)d_in[7];
    const float* abias  = (const float*)d_in[8];
    const int*   nsamp  = (const int*)d_in[9];

    float* out = (float*)d_out;

    // smem floats: supports 32*516 + w 512 + qBuf 28*2*4*64 + combine 14*2*4*32*2
    const int smemFloats = 32 * STRIDE + DN + 28 * 2 * ROWS * QCHUNK + PAIRS_BLK * 2 * ROWS * 32 * 2;
    const int smemBytes = smemFloats * (int)sizeof(float); // ~154 KB
    cudaFuncSetAttribute(resus_kernel,
                         cudaFuncAttributeMaxDynamicSharedMemorySize, smemBytes);

    resus_kernel<<<GRID, THREADS, smemBytes>>>(qenc, senc, sy, sp, qp, w,
                                               ascale, abias, nsamp, out);
}